// round 7
// baseline (speedup 1.0000x reference)
#include <cuda_runtime.h>
#include <math.h>

#define B_ 32
#define C_ 256
#define H_ 56
#define W_ 56
#define HW_ (H_*W_)          // 3136
#define R_ 16
#define HW4_ (HW_/4)         // 784
#define QT8_ 98              // float4 stride for 8-per-thread final (784/8)
#define CG_ 32               // channels per group
#define NCG_ 8               // channel groups

// Scratch — 16B aligned (accessed via float4)
__device__ __align__(16) float g_avg[B_*C_];
__device__ __align__(16) float g_max[B_*C_];
__device__ __align__(16) float g_ca [B_*C_];
__device__ __align__(16) float g_ps [B_*NCG_*HW_];
__device__ __align__(16) float g_pm [B_*NCG_*HW_];
__device__ __align__(16) float g_sa [B_*HW_];

// ---------------------------------------------------------------------------
// Kernel 1: per-(b,c) spatial mean & max. One warp per plane.
// ---------------------------------------------------------------------------
__global__ __launch_bounds__(256) void k_spatial_pool(const float* __restrict__ x) {
    const int warp = threadIdx.x >> 5, lane = threadIdx.x & 31;
    const int bc = blockIdx.x * 8 + warp;
    const float4* __restrict__ xp = (const float4*)(x + (size_t)bc * HW_);
    float s = 0.f, m = -INFINITY;
    #pragma unroll
    for (int batch = 0; batch < 2; batch++) {
        float4 v[12];
        #pragma unroll
        for (int j = 0; j < 12; j++) v[j] = xp[lane + 32 * (batch * 12 + j)];
        #pragma unroll
        for (int j = 0; j < 12; j++) {
            s += (v[j].x + v[j].y) + (v[j].z + v[j].w);
            m = fmaxf(m, fmaxf(fmaxf(v[j].x, v[j].y), fmaxf(v[j].z, v[j].w)));
        }
    }
    if (lane < 16) {
        float4 v = xp[768 + lane];
        s += (v.x + v.y) + (v.z + v.w);
        m = fmaxf(m, fmaxf(fmaxf(v.x, v.y), fmaxf(v.z, v.w)));
    }
    #pragma unroll
    for (int o = 16; o > 0; o >>= 1) {
        s += __shfl_xor_sync(0xffffffffu, s, o);
        m = fmaxf(m, __shfl_xor_sync(0xffffffffu, m, o));
    }
    if (lane == 0) {
        g_avg[bc] = s * (1.0f / HW_);
        g_max[bc] = m;
    }
}

// ---------------------------------------------------------------------------
// Kernel 2: parallel inline MLP + partial channel mean/max of x*ca.
// grid (4 hw-chunks, 8 c-groups, 32 batches) = 1024 blocks.
// ---------------------------------------------------------------------------
__global__ __launch_bounds__(256, 2) void k_chan_pool(const float* __restrict__ x,
                                                      const float* __restrict__ w1,
                                                      const float* __restrict__ w2) {
    const int chunk = blockIdx.x, cg = blockIdx.y, b = blockIdx.z;
    const int t = threadIdx.x;
    __shared__ float sva[C_], svm[C_], hs[R_], sca[C_];

    sva[t] = g_avg[b * C_ + t];
    svm[t] = g_max[b * C_ + t];
    __syncthreads();

    {   // parallel hidden layer: thread t -> (hidden r = t>>4, slice j = t&15)
        const int r = t >> 4, j = t & 15;
        const float* __restrict__ wr = w1 + r * C_ + j * 16;
        const float* __restrict__ va = sva + j * 16;
        const float* __restrict__ vm = svm + j * 16;
        float pa = 0.f, pmx = 0.f;
        #pragma unroll
        for (int i = 0; i < 16; i++) {
            pa  = fmaf(wr[i], va[i], pa);
            pmx = fmaf(wr[i], vm[i], pmx);
        }
        #pragma unroll
        for (int o = 8; o > 0; o >>= 1) {
            pa  += __shfl_down_sync(0xffffffffu, pa,  o, 16);
            pmx += __shfl_down_sync(0xffffffffu, pmx, o, 16);
        }
        if (j == 0) hs[r] = fmaxf(pa, 0.f) + fmaxf(pmx, 0.f);
    }
    __syncthreads();
    {
        float o = 0.f;
        const float* __restrict__ w2r = w2 + t * R_;
        #pragma unroll
        for (int r = 0; r < R_; r++) o = fmaf(w2r[r], hs[r], o);
        float cav = 1.0f / (1.0f + __expf(-o));
        sca[t] = cav;
        if (chunk == 0 && cg == 0) g_ca[b * C_ + t] = cav;
    }
    __syncthreads();

    const int f4 = chunk * 256 + t;
    if (f4 >= HW4_) return;
    const float4* __restrict__ xp =
        (const float4*)(x + (size_t)b * C_ * HW_) + (size_t)cg * CG_ * HW4_ + f4;
    const float* __restrict__ scg = sca + cg * CG_;
    float4 s = make_float4(0.f, 0.f, 0.f, 0.f);
    float4 m = make_float4(-INFINITY, -INFINITY, -INFINITY, -INFINITY);
    #pragma unroll
    for (int batch = 0; batch < 2; batch++) {
        float4 v[16];
        #pragma unroll
        for (int j = 0; j < 16; j++) v[j] = xp[(size_t)(batch * 16 + j) * HW4_];
        #pragma unroll
        for (int j = 0; j < 16; j++) {
            const float a = scg[batch * 16 + j];
            float vx = v[j].x * a, vy = v[j].y * a, vz = v[j].z * a, vw = v[j].w * a;
            s.x += vx; s.y += vy; s.z += vz; s.w += vw;
            m.x = fmaxf(m.x, vx); m.y = fmaxf(m.y, vy);
            m.z = fmaxf(m.z, vz); m.w = fmaxf(m.w, vw);
        }
    }
    const size_t base = ((size_t)b * NCG_ + cg) * HW_;
    ((float4*)(g_ps + base))[f4] = s;
    ((float4*)(g_pm + base))[f4] = m;
}

// ---------------------------------------------------------------------------
// Kernel 3: merge partials (smem tile) + 7x7 conv + sigmoid -> g_sa.
// ---------------------------------------------------------------------------
#define TR 8
#define HR (TR + 6)
#define HF4 (HR * W_ / 4)

__global__ __launch_bounds__(256) void k_sa(const float* __restrict__ wsp) {
    const int b  = blockIdx.y;
    const int h0 = blockIdx.x * TR;
    const int t  = threadIdx.x;

    __shared__ float sw[98];
    __shared__ __align__(16) float spa[HR * W_];
    __shared__ __align__(16) float spm[HR * W_];

    if (t < 98) sw[t] = wsp[t];

    const float* __restrict__ ps = g_ps + (size_t)b * NCG_ * HW_;
    const float* __restrict__ pm = g_pm + (size_t)b * NCG_ * HW_;
    for (int i4 = t; i4 < HF4; i4 += 256) {
        const int r = i4 / (W_ / 4);
        const int hh = h0 - 3 + r;
        float4 s = make_float4(0.f, 0.f, 0.f, 0.f);
        float4 m = make_float4(0.f, 0.f, 0.f, 0.f);
        if (hh >= 0 && hh < H_) {
            const int p4 = hh * (W_ / 4) + (i4 - r * (W_ / 4));
            m = make_float4(-INFINITY, -INFINITY, -INFINITY, -INFINITY);
            #pragma unroll
            for (int g = 0; g < NCG_; g++) {
                float4 vs = ((const float4*)(ps + (size_t)g * HW_))[p4];
                float4 vm = ((const float4*)(pm + (size_t)g * HW_))[p4];
                s.x += vs.x; s.y += vs.y; s.z += vs.z; s.w += vs.w;
                m.x = fmaxf(m.x, vm.x); m.y = fmaxf(m.y, vm.y);
                m.z = fmaxf(m.z, vm.z); m.w = fmaxf(m.w, vm.w);
            }
            const float inv = 1.0f / C_;
            s.x *= inv; s.y *= inv; s.z *= inv; s.w *= inv;
        }
        ((float4*)spa)[i4] = s;
        ((float4*)spm)[i4] = m;
    }
    __syncthreads();

    for (int p = t; p < TR * W_; p += 256) {
        const int hr = p / W_;
        const int wd = p - hr * W_;
        const int h  = h0 + hr;
        float acc = 0.f;
        #pragma unroll
        for (int kh = 0; kh < 7; kh++) {
            const int hh = h + kh - 3;
            if (hh < 0 || hh >= H_) continue;
            const int sr = hh - (h0 - 3);
            #pragma unroll
            for (int kw = 0; kw < 7; kw++) {
                const int ww = wd + kw - 3;
                if (ww < 0 || ww >= W_) continue;
                acc = fmaf(sw[kh * 7 + kw],      spa[sr * W_ + ww], acc);
                acc = fmaf(sw[49 + kh * 7 + kw], spm[sr * W_ + ww], acc);
            }
        }
        g_sa[b * HW_ + h * W_ + wd] = 1.0f / (1.0f + __expf(-acc));
    }
}

// ---------------------------------------------------------------------------
// Kernel 4: out = x * (1 + ca*sa). 8 float4/thread, stride 98 in-plane.
// Streaming stores (evict-first) so out writes don't evict L2-resident x.
// grid = B*C*98/256 = 3136 blocks.
// ---------------------------------------------------------------------------
__device__ __forceinline__ void stcs4(float4* p, float4 v) {
    asm volatile("st.global.cs.v4.f32 [%0], {%1,%2,%3,%4};"
                 :: "l"(p), "f"(v.x), "f"(v.y), "f"(v.z), "f"(v.w) : "memory");
}

__global__ __launch_bounds__(256) void k_final(const float* __restrict__ x,
                                               float* __restrict__ out) {
    const int g = blockIdx.x * 256 + threadIdx.x;    // 0 .. B*C*98-1
    const int plane = g / QT8_;                      // bc
    const int r = g - plane * QT8_;                  // 0..97
    const int b = plane >> 8;
    const float ca = __ldg(&g_ca[plane]);
    const float4* __restrict__ xs = (const float4*)x + (size_t)plane * HW4_ + r;
    const float4* __restrict__ ss = (const float4*)(g_sa + (size_t)b * HW_) + r;
    float4*       __restrict__ os = (float4*)out + (size_t)plane * HW4_ + r;

    float4 v[8], s[8];
    #pragma unroll
    for (int j = 0; j < 8; j++) v[j] = xs[j * QT8_];
    #pragma unroll
    for (int j = 0; j < 8; j++) s[j] = __ldg(ss + j * QT8_);
    #pragma unroll
    for (int j = 0; j < 8; j++) {
        float4 o;
        o.x = v[j].x * fmaf(ca, s[j].x, 1.0f);
        o.y = v[j].y * fmaf(ca, s[j].y, 1.0f);
        o.z = v[j].z * fmaf(ca, s[j].z, 1.0f);
        o.w = v[j].w * fmaf(ca, s[j].w, 1.0f);
        stcs4(os + j * QT8_, o);
    }
}

// ---------------------------------------------------------------------------
extern "C" void kernel_launch(void* const* d_in, const int* in_sizes, int n_in,
                              void* d_out, int out_size) {
    const float* x   = (const float*)d_in[0];
    const float* w1  = (const float*)d_in[1];
    const float* w2  = (const float*)d_in[2];
    const float* wsp = (const float*)d_in[3];
    float* out = (float*)d_out;

    k_spatial_pool<<<1024, 256>>>(x);
    dim3 g2((HW4_ + 255) / 256, NCG_, B_);       // (4, 8, 32) = 1024 blocks
    k_chan_pool<<<g2, 256>>>(x, w1, w2);
    dim3 g3(H_ / TR, B_);                        // (7, 32) = 224 blocks
    k_sa<<<g3, 256>>>(wsp);
    k_final<<<(B_ * C_ * QT8_) / 256, 256>>>(x, out);   // 3136 blocks
}

// round 8
// speedup vs baseline: 1.0011x; 1.0011x over previous
#include <cuda_runtime.h>
#include <math.h>

#define B_ 32
#define C_ 256
#define H_ 56
#define W_ 56
#define HW_ (H_*W_)          // 3136
#define R_ 16
#define HW4_ (HW_/4)         // 784
#define QT8_ 98              // float4 stride for 8-per-thread final (784/8)
#define CG_ 32               // channels per group
#define NCG_ 8               // channel groups

// Scratch — 16B aligned (accessed via float4)
__device__ __align__(16) float g_avg[B_*C_];
__device__ __align__(16) float g_max[B_*C_];
__device__ __align__(16) float g_ca [B_*C_];
__device__ __align__(16) float g_ps [B_*NCG_*HW_];
__device__ __align__(16) float g_pm [B_*NCG_*HW_];
__device__ __align__(16) float g_sa [B_*HW_];

// ---------------------------------------------------------------------------
// Kernel 1: per-(b,c) spatial mean & max. One warp per plane. FORWARD order.
// ---------------------------------------------------------------------------
__global__ __launch_bounds__(256) void k_spatial_pool(const float* __restrict__ x) {
    const int warp = threadIdx.x >> 5, lane = threadIdx.x & 31;
    const int bc = blockIdx.x * 8 + warp;
    const float4* __restrict__ xp = (const float4*)(x + (size_t)bc * HW_);
    float s = 0.f, m = -INFINITY;
    #pragma unroll
    for (int batch = 0; batch < 2; batch++) {
        float4 v[12];
        #pragma unroll
        for (int j = 0; j < 12; j++) v[j] = xp[lane + 32 * (batch * 12 + j)];
        #pragma unroll
        for (int j = 0; j < 12; j++) {
            s += (v[j].x + v[j].y) + (v[j].z + v[j].w);
            m = fmaxf(m, fmaxf(fmaxf(v[j].x, v[j].y), fmaxf(v[j].z, v[j].w)));
        }
    }
    if (lane < 16) {
        float4 v = xp[768 + lane];
        s += (v.x + v.y) + (v.z + v.w);
        m = fmaxf(m, fmaxf(fmaxf(v.x, v.y), fmaxf(v.z, v.w)));
    }
    #pragma unroll
    for (int o = 16; o > 0; o >>= 1) {
        s += __shfl_xor_sync(0xffffffffu, s, o);
        m = fmaxf(m, __shfl_xor_sync(0xffffffffu, m, o));
    }
    if (lane == 0) {
        g_avg[bc] = s * (1.0f / HW_);
        g_max[bc] = m;
    }
}

// ---------------------------------------------------------------------------
// Kernel 2: parallel inline MLP + partial channel mean/max of x*ca.
// grid (4, 8, 32) = 1024 blocks. REVERSED traversal: starts at the x region
// k_spatial_pool touched last (b=31, high c), so those reads hit L2.
// ---------------------------------------------------------------------------
__global__ __launch_bounds__(256, 2) void k_chan_pool(const float* __restrict__ x,
                                                      const float* __restrict__ w1,
                                                      const float* __restrict__ w2) {
    const int chunk = 3 - blockIdx.x;
    const int cg    = (NCG_ - 1) - blockIdx.y;
    const int b     = (B_ - 1) - blockIdx.z;
    const int t = threadIdx.x;
    __shared__ float sva[C_], svm[C_], hs[R_], sca[C_];

    sva[t] = g_avg[b * C_ + t];
    svm[t] = g_max[b * C_ + t];
    __syncthreads();

    {   // parallel hidden layer: thread t -> (hidden r = t>>4, slice j = t&15)
        const int r = t >> 4, j = t & 15;
        const float* __restrict__ wr = w1 + r * C_ + j * 16;
        const float* __restrict__ va = sva + j * 16;
        const float* __restrict__ vm = svm + j * 16;
        float pa = 0.f, pmx = 0.f;
        #pragma unroll
        for (int i = 0; i < 16; i++) {
            pa  = fmaf(wr[i], va[i], pa);
            pmx = fmaf(wr[i], vm[i], pmx);
        }
        #pragma unroll
        for (int o = 8; o > 0; o >>= 1) {
            pa  += __shfl_down_sync(0xffffffffu, pa,  o, 16);
            pmx += __shfl_down_sync(0xffffffffu, pmx, o, 16);
        }
        if (j == 0) hs[r] = fmaxf(pa, 0.f) + fmaxf(pmx, 0.f);
    }
    __syncthreads();
    {
        float o = 0.f;
        const float* __restrict__ w2r = w2 + t * R_;
        #pragma unroll
        for (int r = 0; r < R_; r++) o = fmaf(w2r[r], hs[r], o);
        float cav = 1.0f / (1.0f + __expf(-o));
        sca[t] = cav;
        if (chunk == 0 && cg == 0) g_ca[b * C_ + t] = cav;
    }
    __syncthreads();

    const int f4 = chunk * 256 + t;
    if (f4 >= HW4_) return;
    const float4* __restrict__ xp =
        (const float4*)(x + (size_t)b * C_ * HW_) + (size_t)cg * CG_ * HW4_ + f4;
    const float* __restrict__ scg = sca + cg * CG_;
    float4 s = make_float4(0.f, 0.f, 0.f, 0.f);
    float4 m = make_float4(-INFINITY, -INFINITY, -INFINITY, -INFINITY);
    #pragma unroll
    for (int batch = 0; batch < 2; batch++) {
        float4 v[16];
        #pragma unroll
        for (int j = 0; j < 16; j++) v[j] = xp[(size_t)(batch * 16 + j) * HW4_];
        #pragma unroll
        for (int j = 0; j < 16; j++) {
            const float a = scg[batch * 16 + j];
            float vx = v[j].x * a, vy = v[j].y * a, vz = v[j].z * a, vw = v[j].w * a;
            s.x += vx; s.y += vy; s.z += vz; s.w += vw;
            m.x = fmaxf(m.x, vx); m.y = fmaxf(m.y, vy);
            m.z = fmaxf(m.z, vz); m.w = fmaxf(m.w, vw);
        }
    }
    const size_t base = ((size_t)b * NCG_ + cg) * HW_;
    ((float4*)(g_ps + base))[f4] = s;
    ((float4*)(g_pm + base))[f4] = m;
}

// ---------------------------------------------------------------------------
// Kernel 3: merge partials (smem tile) + 7x7 conv + sigmoid -> g_sa.
// ---------------------------------------------------------------------------
#define TR 8
#define HR (TR + 6)
#define HF4 (HR * W_ / 4)

__global__ __launch_bounds__(256) void k_sa(const float* __restrict__ wsp) {
    const int b  = blockIdx.y;
    const int h0 = blockIdx.x * TR;
    const int t  = threadIdx.x;

    __shared__ float sw[98];
    __shared__ __align__(16) float spa[HR * W_];
    __shared__ __align__(16) float spm[HR * W_];

    if (t < 98) sw[t] = wsp[t];

    const float* __restrict__ ps = g_ps + (size_t)b * NCG_ * HW_;
    const float* __restrict__ pm = g_pm + (size_t)b * NCG_ * HW_;
    for (int i4 = t; i4 < HF4; i4 += 256) {
        const int r = i4 / (W_ / 4);
        const int hh = h0 - 3 + r;
        float4 s = make_float4(0.f, 0.f, 0.f, 0.f);
        float4 m = make_float4(0.f, 0.f, 0.f, 0.f);
        if (hh >= 0 && hh < H_) {
            const int p4 = hh * (W_ / 4) + (i4 - r * (W_ / 4));
            m = make_float4(-INFINITY, -INFINITY, -INFINITY, -INFINITY);
            #pragma unroll
            for (int g = 0; g < NCG_; g++) {
                float4 vs = ((const float4*)(ps + (size_t)g * HW_))[p4];
                float4 vm = ((const float4*)(pm + (size_t)g * HW_))[p4];
                s.x += vs.x; s.y += vs.y; s.z += vs.z; s.w += vs.w;
                m.x = fmaxf(m.x, vm.x); m.y = fmaxf(m.y, vm.y);
                m.z = fmaxf(m.z, vm.z); m.w = fmaxf(m.w, vm.w);
            }
            const float inv = 1.0f / C_;
            s.x *= inv; s.y *= inv; s.z *= inv; s.w *= inv;
        }
        ((float4*)spa)[i4] = s;
        ((float4*)spm)[i4] = m;
    }
    __syncthreads();

    for (int p = t; p < TR * W_; p += 256) {
        const int hr = p / W_;
        const int wd = p - hr * W_;
        const int h  = h0 + hr;
        float acc = 0.f;
        #pragma unroll
        for (int kh = 0; kh < 7; kh++) {
            const int hh = h + kh - 3;
            if (hh < 0 || hh >= H_) continue;
            const int sr = hh - (h0 - 3);
            #pragma unroll
            for (int kw = 0; kw < 7; kw++) {
                const int ww = wd + kw - 3;
                if (ww < 0 || ww >= W_) continue;
                acc = fmaf(sw[kh * 7 + kw],      spa[sr * W_ + ww], acc);
                acc = fmaf(sw[49 + kh * 7 + kw], spm[sr * W_ + ww], acc);
            }
        }
        g_sa[b * HW_ + h * W_ + wd] = 1.0f / (1.0f + __expf(-acc));
    }
}

// ---------------------------------------------------------------------------
// Kernel 4: out = x * (1 + ca*sa). 8 float4/thread, stride 98 in-plane.
// FORWARD order: plane 0 first — matches where reversed chan_pool ended,
// so early x reads hit L2. Streaming stores keep out from evicting x.
// grid = B*C*98/256 = 3136 blocks.
// ---------------------------------------------------------------------------
__device__ __forceinline__ void stcs4(float4* p, float4 v) {
    asm volatile("st.global.cs.v4.f32 [%0], {%1,%2,%3,%4};"
                 :: "l"(p), "f"(v.x), "f"(v.y), "f"(v.z), "f"(v.w) : "memory");
}

__global__ __launch_bounds__(256) void k_final(const float* __restrict__ x,
                                               float* __restrict__ out) {
    const int g = blockIdx.x * 256 + threadIdx.x;    // 0 .. B*C*98-1
    const int plane = g / QT8_;                      // bc
    const int r = g - plane * QT8_;                  // 0..97
    const int b = plane >> 8;
    const float ca = __ldg(&g_ca[plane]);
    const float4* __restrict__ xs = (const float4*)x + (size_t)plane * HW4_ + r;
    const float4* __restrict__ ss = (const float4*)(g_sa + (size_t)b * HW_) + r;
    float4*       __restrict__ os = (float4*)out + (size_t)plane * HW4_ + r;

    float4 v[8], s[8];
    #pragma unroll
    for (int j = 0; j < 8; j++) v[j] = xs[j * QT8_];
    #pragma unroll
    for (int j = 0; j < 8; j++) s[j] = __ldg(ss + j * QT8_);
    #pragma unroll
    for (int j = 0; j < 8; j++) {
        float4 o;
        o.x = v[j].x * fmaf(ca, s[j].x, 1.0f);
        o.y = v[j].y * fmaf(ca, s[j].y, 1.0f);
        o.z = v[j].z * fmaf(ca, s[j].z, 1.0f);
        o.w = v[j].w * fmaf(ca, s[j].w, 1.0f);
        stcs4(os + j * QT8_, o);
    }
}

// ---------------------------------------------------------------------------
extern "C" void kernel_launch(void* const* d_in, const int* in_sizes, int n_in,
                              void* d_out, int out_size) {
    const float* x   = (const float*)d_in[0];
    const float* w1  = (const float*)d_in[1];
    const float* w2  = (const float*)d_in[2];
    const float* wsp = (const float*)d_in[3];
    float* out = (float*)d_out;

    k_spatial_pool<<<1024, 256>>>(x);
    dim3 g2((HW4_ + 255) / 256, NCG_, B_);       // (4, 8, 32) = 1024 blocks
    k_chan_pool<<<g2, 256>>>(x, w1, w2);
    dim3 g3(H_ / TR, B_);                        // (7, 32) = 224 blocks
    k_sa<<<g3, 256>>>(wsp);
    k_final<<<(B_ * C_ * QT8_) / 256, 256>>>(x, out);   // 3136 blocks
}

// round 10
// speedup vs baseline: 1.0095x; 1.0084x over previous
#include <cuda_runtime.h>
#include <math.h>

#define B_ 32
#define C_ 256
#define H_ 56
#define W_ 56
#define HW_ (H_*W_)          // 3136
#define R_ 16
#define HW4_ (HW_/4)         // 784
#define HW8_ (HW_/8)         // 392 float8 per plane
#define QF8_ 98              // f8 stride for 4-per-thread final (392/4)
#define CG_ 32               // channels per group
#define NCG_ 8               // channel groups

// Scratch — 32B aligned
__device__ __align__(32) float g_avg[B_*C_];
__device__ __align__(32) float g_max[B_*C_];
__device__ __align__(32) float g_ca [B_*C_];
__device__ __align__(32) float g_ps [B_*NCG_*HW_];
__device__ __align__(32) float g_pm [B_*NCG_*HW_];
__device__ __align__(32) float g_sa [B_*HW_];

// ---- 32-byte loads with L2 eviction priority --------------------------------
__device__ __forceinline__ void ldg_evl8(const float* p, float4& lo, float4& hi) {
    unsigned long long r0, r1, r2, r3;
    asm volatile("ld.global.nc.L2::evict_last.v4.b64 {%0,%1,%2,%3}, [%4];"
                 : "=l"(r0), "=l"(r1), "=l"(r2), "=l"(r3) : "l"(p));
    lo.x = __uint_as_float((unsigned)r0); lo.y = __uint_as_float((unsigned)(r0 >> 32));
    lo.z = __uint_as_float((unsigned)r1); lo.w = __uint_as_float((unsigned)(r1 >> 32));
    hi.x = __uint_as_float((unsigned)r2); hi.y = __uint_as_float((unsigned)(r2 >> 32));
    hi.z = __uint_as_float((unsigned)r3); hi.w = __uint_as_float((unsigned)(r3 >> 32));
}
__device__ __forceinline__ void ldg_evf8(const float* p, float4& lo, float4& hi) {
    unsigned long long r0, r1, r2, r3;
    asm volatile("ld.global.nc.L2::evict_first.v4.b64 {%0,%1,%2,%3}, [%4];"
                 : "=l"(r0), "=l"(r1), "=l"(r2), "=l"(r3) : "l"(p));
    lo.x = __uint_as_float((unsigned)r0); lo.y = __uint_as_float((unsigned)(r0 >> 32));
    lo.z = __uint_as_float((unsigned)r1); lo.w = __uint_as_float((unsigned)(r1 >> 32));
    hi.x = __uint_as_float((unsigned)r2); hi.y = __uint_as_float((unsigned)(r2 >> 32));
    hi.z = __uint_as_float((unsigned)r3); hi.w = __uint_as_float((unsigned)(r3 >> 32));
}

// ---------------------------------------------------------------------------
// Kernel 1: per-(b,c) spatial mean & max. One warp per plane, 32B loads.
// 392 f8 per plane = 32 lanes * 12 + 8 tail.
// ---------------------------------------------------------------------------
__global__ __launch_bounds__(256) void k_spatial_pool(const float* __restrict__ x) {
    const int warp = threadIdx.x >> 5, lane = threadIdx.x & 31;
    const int bc = blockIdx.x * 8 + warp;
    const float* __restrict__ xp = x + (size_t)bc * HW_;
    float s = 0.f, m = -INFINITY;
    #pragma unroll
    for (int batch = 0; batch < 2; batch++) {
        float4 lo[6], hi[6];
        #pragma unroll
        for (int j = 0; j < 6; j++)
            ldg_evl8(xp + (size_t)(lane + 32 * (batch * 6 + j)) * 8, lo[j], hi[j]);
        #pragma unroll
        for (int j = 0; j < 6; j++) {
            s += ((lo[j].x + lo[j].y) + (lo[j].z + lo[j].w))
               + ((hi[j].x + hi[j].y) + (hi[j].z + hi[j].w));
            float m1 = fmaxf(fmaxf(lo[j].x, lo[j].y), fmaxf(lo[j].z, lo[j].w));
            float m2 = fmaxf(fmaxf(hi[j].x, hi[j].y), fmaxf(hi[j].z, hi[j].w));
            m = fmaxf(m, fmaxf(m1, m2));
        }
    }
    if (lane < 8) {
        float4 lo, hi;
        ldg_evl8(xp + (size_t)(384 + lane) * 8, lo, hi);
        s += ((lo.x + lo.y) + (lo.z + lo.w)) + ((hi.x + hi.y) + (hi.z + hi.w));
        float m1 = fmaxf(fmaxf(lo.x, lo.y), fmaxf(lo.z, lo.w));
        float m2 = fmaxf(fmaxf(hi.x, hi.y), fmaxf(hi.z, hi.w));
        m = fmaxf(m, fmaxf(m1, m2));
    }
    #pragma unroll
    for (int o = 16; o > 0; o >>= 1) {
        s += __shfl_xor_sync(0xffffffffu, s, o);
        m = fmaxf(m, __shfl_xor_sync(0xffffffffu, m, o));
    }
    if (lane == 0) {
        g_avg[bc] = s * (1.0f / HW_);
        g_max[bc] = m;
    }
}

// ---------------------------------------------------------------------------
// Kernel 1b: channel-attention MLP, one block per batch -> g_ca.
// ---------------------------------------------------------------------------
__global__ __launch_bounds__(256) void k_mlp(const float* __restrict__ w1,
                                             const float* __restrict__ w2) {
    const int b = blockIdx.x;
    const int t = threadIdx.x;
    __shared__ float sva[C_], svm[C_], hs[R_];
    sva[t] = g_avg[b * C_ + t];
    svm[t] = g_max[b * C_ + t];
    __syncthreads();
    {
        const int r = t >> 4, j = t & 15;
        const float* __restrict__ wr = w1 + r * C_ + j * 16;
        const float* __restrict__ va = sva + j * 16;
        const float* __restrict__ vm = svm + j * 16;
        float pa = 0.f, pmx = 0.f;
        #pragma unroll
        for (int i = 0; i < 16; i++) {
            pa  = fmaf(wr[i], va[i], pa);
            pmx = fmaf(wr[i], vm[i], pmx);
        }
        #pragma unroll
        for (int o = 8; o > 0; o >>= 1) {
            pa  += __shfl_down_sync(0xffffffffu, pa,  o, 16);
            pmx += __shfl_down_sync(0xffffffffu, pmx, o, 16);
        }
        if (j == 0) hs[r] = fmaxf(pa, 0.f) + fmaxf(pmx, 0.f);
    }
    __syncthreads();
    float o = 0.f;
    const float* __restrict__ w2r = w2 + t * R_;
    #pragma unroll
    for (int r = 0; r < R_; r++) o = fmaf(w2r[r], hs[r], o);
    g_ca[b * C_ + t] = 1.0f / (1.0f + __expf(-o));
}

// ---------------------------------------------------------------------------
// Kernel 2: partial channel mean/max of x*ca. grid (2, 8, 32) = 512 blocks.
// 32B evict_last loads; thread owns one f8 position, loops 32 channels.
// ---------------------------------------------------------------------------
__global__ __launch_bounds__(256, 2) void k_chan_pool(const float* __restrict__ x) {
    const int chunk = blockIdx.x, cg = blockIdx.y, b = blockIdx.z;
    const int t = threadIdx.x;
    __shared__ float sca[C_];
    sca[t] = g_ca[b * C_ + t];
    __syncthreads();

    const int f8 = chunk * 256 + t;
    if (f8 >= HW8_) return;
    const float* __restrict__ xb =
        x + (size_t)b * C_ * HW_ + (size_t)cg * CG_ * HW_ + (size_t)f8 * 8;
    const float* __restrict__ scg = sca + cg * CG_;
    float4 slo = make_float4(0.f, 0.f, 0.f, 0.f), shi = slo;
    float4 mlo = make_float4(-INFINITY, -INFINITY, -INFINITY, -INFINITY), mhi = mlo;
    #pragma unroll
    for (int batch = 0; batch < 4; batch++) {
        float4 lo[8], hi[8];
        #pragma unroll
        for (int j = 0; j < 8; j++)
            ldg_evl8(xb + (size_t)(batch * 8 + j) * HW_, lo[j], hi[j]);
        #pragma unroll
        for (int j = 0; j < 8; j++) {
            const float a = scg[batch * 8 + j];
            float v0 = lo[j].x * a, v1 = lo[j].y * a, v2 = lo[j].z * a, v3 = lo[j].w * a;
            float v4 = hi[j].x * a, v5 = hi[j].y * a, v6 = hi[j].z * a, v7 = hi[j].w * a;
            slo.x += v0; slo.y += v1; slo.z += v2; slo.w += v3;
            shi.x += v4; shi.y += v5; shi.z += v6; shi.w += v7;
            mlo.x = fmaxf(mlo.x, v0); mlo.y = fmaxf(mlo.y, v1);
            mlo.z = fmaxf(mlo.z, v2); mlo.w = fmaxf(mlo.w, v3);
            mhi.x = fmaxf(mhi.x, v4); mhi.y = fmaxf(mhi.y, v5);
            mhi.z = fmaxf(mhi.z, v6); mhi.w = fmaxf(mhi.w, v7);
        }
    }
    const size_t base = ((size_t)b * NCG_ + cg) * HW_;
    float4* __restrict__ pav = (float4*)(g_ps + base);
    float4* __restrict__ pmx = (float4*)(g_pm + base);
    pav[f8 * 2]     = slo;
    pav[f8 * 2 + 1] = shi;
    pmx[f8 * 2]     = mlo;
    pmx[f8 * 2 + 1] = mhi;
}

// ---------------------------------------------------------------------------
// Kernel 3: merge partials (smem tile) + 7x7 conv + sigmoid -> g_sa.
// ---------------------------------------------------------------------------
#define TR 8
#define HR (TR + 6)
#define HF4 (HR * W_ / 4)

__global__ __launch_bounds__(256) void k_sa(const float* __restrict__ wsp) {
    const int b  = blockIdx.y;
    const int h0 = blockIdx.x * TR;
    const int t  = threadIdx.x;

    __shared__ float sw[98];
    __shared__ __align__(16) float spa[HR * W_];
    __shared__ __align__(16) float spm[HR * W_];

    if (t < 98) sw[t] = wsp[t];

    const float* __restrict__ ps = g_ps + (size_t)b * NCG_ * HW_;
    const float* __restrict__ pm = g_pm + (size_t)b * NCG_ * HW_;
    for (int i4 = t; i4 < HF4; i4 += 256) {
        const int r = i4 / (W_ / 4);
        const int hh = h0 - 3 + r;
        float4 s = make_float4(0.f, 0.f, 0.f, 0.f);
        float4 m = make_float4(0.f, 0.f, 0.f, 0.f);
        if (hh >= 0 && hh < H_) {
            const int p4 = hh * (W_ / 4) + (i4 - r * (W_ / 4));
            m = make_float4(-INFINITY, -INFINITY, -INFINITY, -INFINITY);
            #pragma unroll
            for (int g = 0; g < NCG_; g++) {
                float4 vs = ((const float4*)(ps + (size_t)g * HW_))[p4];
                float4 vm = ((const float4*)(pm + (size_t)g * HW_))[p4];
                s.x += vs.x; s.y += vs.y; s.z += vs.z; s.w += vs.w;
                m.x = fmaxf(m.x, vm.x); m.y = fmaxf(m.y, vm.y);
                m.z = fmaxf(m.z, vm.z); m.w = fmaxf(m.w, vm.w);
            }
            const float inv = 1.0f / C_;
            s.x *= inv; s.y *= inv; s.z *= inv; s.w *= inv;
        }
        ((float4*)spa)[i4] = s;
        ((float4*)spm)[i4] = m;
    }
    __syncthreads();

    for (int p = t; p < TR * W_; p += 256) {
        const int hr = p / W_;
        const int wd = p - hr * W_;
        const int h  = h0 + hr;
        float acc = 0.f;
        #pragma unroll
        for (int kh = 0; kh < 7; kh++) {
            const int hh = h + kh - 3;
            if (hh < 0 || hh >= H_) continue;
            const int sr = hh - (h0 - 3);
            #pragma unroll
            for (int kw = 0; kw < 7; kw++) {
                const int ww = wd + kw - 3;
                if (ww < 0 || ww >= W_) continue;
                acc = fmaf(sw[kh * 7 + kw],      spa[sr * W_ + ww], acc);
                acc = fmaf(sw[49 + kh * 7 + kw], spm[sr * W_ + ww], acc);
            }
        }
        g_sa[b * HW_ + h * W_ + wd] = 1.0f / (1.0f + __expf(-acc));
    }
}

// ---------------------------------------------------------------------------
// Kernel 4: out = x * (1 + ca*sa). 4 f8 per thread (stride 98 f8 in-plane).
// x read with evict_first 32B loads.
// ---------------------------------------------------------------------------
__global__ __launch_bounds__(256) void k_final(const float* __restrict__ x,
                                               float* __restrict__ out) {
    const int g = blockIdx.x * 256 + threadIdx.x;    // 0 .. B*C*98-1
    const int plane = g / QF8_;
    const int r = g - plane * QF8_;                  // 0..97 (f8 units)
    const int b = plane >> 8;
    const float ca = __ldg(&g_ca[plane]);
    const float*  __restrict__ xs = x + (size_t)plane * HW_ + (size_t)r * 8;
    const float4* __restrict__ ss = (const float4*)(g_sa + (size_t)b * HW_) + r * 2;
    float4*       __restrict__ os = (float4*)(out + (size_t)plane * HW_) + r * 2;

    float4 vlo[4], vhi[4], slo[4], shi[4];
    #pragma unroll
    for (int j = 0; j < 4; j++)
        ldg_evf8(xs + (size_t)j * QF8_ * 8, vlo[j], vhi[j]);
    #pragma unroll
    for (int j = 0; j < 4; j++) {
        slo[j] = __ldg(ss + j * QF8_ * 2);
        shi[j] = __ldg(ss + j * QF8_ * 2 + 1);
    }
    #pragma unroll
    for (int j = 0; j < 4; j++) {
        float4 o1, o2;
        o1.x = vlo[j].x * fmaf(ca, slo[j].x, 1.0f);
        o1.y = vlo[j].y * fmaf(ca, slo[j].y, 1.0f);
        o1.z = vlo[j].z * fmaf(ca, slo[j].z, 1.0f);
        o1.w = vlo[j].w * fmaf(ca, slo[j].w, 1.0f);
        o2.x = vhi[j].x * fmaf(ca, shi[j].x, 1.0f);
        o2.y = vhi[j].y * fmaf(ca, shi[j].y, 1.0f);
        o2.z = vhi[j].z * fmaf(ca, shi[j].z, 1.0f);
        o2.w = vhi[j].w * fmaf(ca, shi[j].w, 1.0f);
        os[j * QF8_ * 2]     = o1;
        os[j * QF8_ * 2 + 1] = o2;
    }
}

// ---------------------------------------------------------------------------
extern "C" void kernel_launch(void* const* d_in, const int* in_sizes, int n_in,
                              void* d_out, int out_size) {
    const float* x   = (const float*)d_in[0];
    const float* w1  = (const float*)d_in[1];
    const float* w2  = (const float*)d_in[2];
    const float* wsp = (const float*)d_in[3];
    float* out = (float*)d_out;

    k_spatial_pool<<<1024, 256>>>(x);
    k_mlp<<<B_, 256>>>(w1, w2);
    dim3 g2((HW8_ + 255) / 256, NCG_, B_);       // (2, 8, 32) = 512 blocks
    k_chan_pool<<<g2, 256>>>(x);
    dim3 g3(H_ / TR, B_);                        // (7, 32) = 224 blocks
    k_sa<<<g3, 256>>>(wsp);
    k_final<<<(B_ * C_ * QF8_) / 256, 256>>>(x, out);   // 3136 blocks
}